// round 7
// baseline (speedup 1.0000x reference)
#include <cuda_runtime.h>
#include <math.h>
#include <stdint.h>

#define N_AG 65536
#define G_NUM 1024

static __device__ float g_inter_emb[(size_t)N_AG * 64];
static __device__ float g_intra_emb[(size_t)N_AG * 64];
static __device__ float g_qkv[(size_t)N_AG * 384];
static __device__ float g_att[(size_t)N_AG * 128];
static __device__ float g_pooled[G_NUM * 64];
static __device__ float g_qkv_inter[G_NUM * 384];
static __device__ float g_att_inter[G_NUM * 128];

__device__ __forceinline__ uint32_t f2tf32(float x) {
    uint32_t u;
    asm("cvt.rna.tf32.f32 %0, %1;" : "=r"(u) : "f"(x));
    return u;
}

__device__ __forceinline__ void mma_tf32(float* c, const uint32_t* a, const uint32_t* b) {
    asm volatile("mma.sync.aligned.m16n8k8.row.col.f32.tf32.tf32.f32 "
        "{%0,%1,%2,%3}, {%4,%5,%6,%7}, {%8,%9}, {%0,%1,%2,%3};"
        : "+f"(c[0]), "+f"(c[1]), "+f"(c[2]), "+f"(c[3])
        : "r"(a[0]), "r"(a[1]), "r"(a[2]), "r"(a[3]), "r"(b[0]), "r"(b[1]));
}

// Permuted column for K-chunk element k (0..31): pairs (t, t+4) adjacent.
// col = (k8)*8 + 2*e + parity, where store side uses e = element in float4, parity = kq&1.

// ================= Kernel A: embedding GEMM (TF32 MMA, occ-2, LDS.64 frags) =================
__global__ void __launch_bounds__(256, 2) k_emb_tc(const float* __restrict__ obs,
    const float* __restrict__ lw, const float* __restrict__ lb,
    const float* __restrict__ iew, const float* __restrict__ ieb,
    const float* __restrict__ aew, const float* __restrict__ aeb,
    float* __restrict__ out)
{
    __shared__ uint32_t As[128][40];
    __shared__ uint32_t Ws[128][40];
    const int tid = threadIdx.x;
    const int lane = tid & 31, warp = tid >> 5;
    const int wm = warp >> 2, wn = warp & 3;
    const int gid = lane >> 2, tg = lane & 3;
    const int m0 = blockIdx.x * 128, j0 = blockIdx.y * 128;

    float acc[4][4][4];
#pragma unroll
    for (int i = 0; i < 4; i++)
#pragma unroll
        for (int j = 0; j < 4; j++)
#pragma unroll
            for (int u = 0; u < 4; u++) acc[i][j][u] = 0.f;

    for (int k0 = 0; k0 < 256; k0 += 32) {
#pragma unroll
        for (int l = 0; l < 4; l++) {
            int slot = tid + l * 256;
            int r = slot >> 3, kq = slot & 7;
            int base = ((kq >> 1) << 3) + (kq & 1);
            float4 va = *(const float4*)(obs + (size_t)(m0 + r) * 256 + k0 + kq * 4);
            As[r][base+0] = f2tf32(va.x); As[r][base+2] = f2tf32(va.y);
            As[r][base+4] = f2tf32(va.z); As[r][base+6] = f2tf32(va.w);
            int j = j0 + r;
            const float* wr = (j < 512) ? (lw + (size_t)j * 256)
                            : (j < 576) ? (iew + (size_t)(j - 512) * 256)
                            : (aew + (size_t)(j - 576) * 256);
            float4 vw = *(const float4*)(wr + k0 + kq * 4);
            Ws[r][base+0] = f2tf32(vw.x); Ws[r][base+2] = f2tf32(vw.y);
            Ws[r][base+4] = f2tf32(vw.z); Ws[r][base+6] = f2tf32(vw.w);
        }
        __syncthreads();
#pragma unroll
        for (int k8 = 0; k8 < 4; k8++) {
            int kb = k8 * 8 + 2 * tg;
            uint32_t a[4][4], b[4][2];
#pragma unroll
            for (int mt = 0; mt < 4; mt++) {
                int row = wm * 64 + mt * 16;
                uint2 p = *(const uint2*)&As[row + gid][kb];
                uint2 q = *(const uint2*)&As[row + gid + 8][kb];
                a[mt][0] = p.x; a[mt][1] = q.x; a[mt][2] = p.y; a[mt][3] = q.y;
            }
#pragma unroll
            for (int nt = 0; nt < 4; nt++) {
                int col = wn * 32 + nt * 8;
                uint2 qb = *(const uint2*)&Ws[col + gid][kb];
                b[nt][0] = qb.x; b[nt][1] = qb.y;
            }
#pragma unroll
            for (int mt = 0; mt < 4; mt++)
#pragma unroll
                for (int nt = 0; nt < 4; nt++)
                    mma_tf32(acc[mt][nt], a[mt], b[nt]);
        }
        __syncthreads();
    }

#pragma unroll
    for (int mt = 0; mt < 4; mt++) {
#pragma unroll
        for (int nt = 0; nt < 4; nt++) {
            int col = j0 + wn * 32 + nt * 8 + 2 * tg;
#pragma unroll
            for (int half = 0; half < 2; half++) {
                int row = m0 + wm * 64 + mt * 16 + gid + half * 8;
                float v0 = acc[mt][nt][half * 2 + 0];
                float v1 = acc[mt][nt][half * 2 + 1];
                float2 r2;
                if (col < 512) {
                    r2.x = tanhf(v0 + lb[col]); r2.y = tanhf(v1 + lb[col + 1]);
                    *(float2*)(out + (size_t)row * 640 + col) = r2;
                } else if (col < 576) {
                    int c = col - 512;
                    r2.x = tanhf(v0 + ieb[c]); r2.y = tanhf(v1 + ieb[c + 1]);
                    *(float2*)(g_inter_emb + (size_t)row * 64 + c) = r2;
                } else {
                    int c = col - 576;
                    r2.x = tanhf(v0 + aeb[c]); r2.y = tanhf(v1 + aeb[c + 1]);
                    *(float2*)(g_intra_emb + (size_t)row * 64 + c) = r2;
                }
            }
        }
    }
}

// ============ Kernel B: intra QKV GEMM (TF32 MMA, gathered A, occ-2) ============
__global__ void __launch_bounds__(256, 2) k_qkv_tc(const int* __restrict__ sets,
    const float* __restrict__ wmu, const float* __restrict__ bmu,
    const float* __restrict__ wsd, const float* __restrict__ bsd)
{
    __shared__ uint32_t As[128][40];
    __shared__ uint32_t Ws[128][40];
    const int tid = threadIdx.x;
    const int lane = tid & 31, warp = tid >> 5;
    const int wm = warp >> 2, wn = warp & 3;
    const int gid = lane >> 2, tg = lane & 3;
    const int m0 = blockIdx.x * 128, j0 = blockIdx.y * 128;

    float acc[4][4][4];
#pragma unroll
    for (int i = 0; i < 4; i++)
#pragma unroll
        for (int j = 0; j < 4; j++)
#pragma unroll
            for (int u = 0; u < 4; u++) acc[i][j][u] = 0.f;

#pragma unroll
    for (int k0 = 0; k0 < 64; k0 += 32) {
#pragma unroll
        for (int l = 0; l < 4; l++) {
            int slot = tid + l * 256;
            int r = slot >> 3, kq = slot & 7;
            int base = ((kq >> 1) << 3) + (kq & 1);
            int src = sets[m0 + r];
            float4 va = *(const float4*)(g_intra_emb + (size_t)src * 64 + k0 + kq * 4);
            As[r][base+0] = f2tf32(va.x); As[r][base+2] = f2tf32(va.y);
            As[r][base+4] = f2tf32(va.z); As[r][base+6] = f2tf32(va.w);
            int j = j0 + r;
            const float* wr = (j < 192) ? (wmu + (size_t)j * 64) : (wsd + (size_t)(j - 192) * 64);
            float4 vw = *(const float4*)(wr + k0 + kq * 4);
            Ws[r][base+0] = f2tf32(vw.x); Ws[r][base+2] = f2tf32(vw.y);
            Ws[r][base+4] = f2tf32(vw.z); Ws[r][base+6] = f2tf32(vw.w);
        }
        __syncthreads();
#pragma unroll
        for (int k8 = 0; k8 < 4; k8++) {
            int kb = k8 * 8 + 2 * tg;
            uint32_t a[4][4], b[4][2];
#pragma unroll
            for (int mt = 0; mt < 4; mt++) {
                int row = wm * 64 + mt * 16;
                uint2 p = *(const uint2*)&As[row + gid][kb];
                uint2 q = *(const uint2*)&As[row + gid + 8][kb];
                a[mt][0] = p.x; a[mt][1] = q.x; a[mt][2] = p.y; a[mt][3] = q.y;
            }
#pragma unroll
            for (int nt = 0; nt < 4; nt++) {
                int col = wn * 32 + nt * 8;
                uint2 qb = *(const uint2*)&Ws[col + gid][kb];
                b[nt][0] = qb.x; b[nt][1] = qb.y;
            }
#pragma unroll
            for (int mt = 0; mt < 4; mt++)
#pragma unroll
                for (int nt = 0; nt < 4; nt++)
                    mma_tf32(acc[mt][nt], a[mt], b[nt]);
        }
        __syncthreads();
    }

#pragma unroll
    for (int mt = 0; mt < 4; mt++) {
#pragma unroll
        for (int nt = 0; nt < 4; nt++) {
            int col = j0 + wn * 32 + nt * 8 + 2 * tg;
            float b0 = (col < 192) ? bmu[col] : bsd[col - 192];
            float b1 = (col + 1 < 192) ? bmu[col + 1] : bsd[col + 1 - 192];
#pragma unroll
            for (int half = 0; half < 2; half++) {
                int row = m0 + wm * 64 + mt * 16 + gid + half * 8;
                float2 r2;
                r2.x = acc[mt][nt][half * 2 + 0] + b0;
                r2.y = acc[mt][nt][half * 2 + 1] + b1;
                *(float2*)(g_qkv + (size_t)row * 384 + col) = r2;
            }
        }
    }
}

// ---- Kernel C: intra attention, single pass ----
__global__ void __launch_bounds__(256) k_intra_attn()
{
    __shared__ float sk[64 * 64];
    __shared__ float sv[64 * 64];
    const int g = blockIdx.x, which = blockIdx.y, tid = threadIdx.x;
#pragma unroll
    for (int l = 0; l < 8; l++) {
        int idx = tid + l * 256;
        int kv = idx >> 10, r = (idx >> 4) & 63, dq = idx & 15;
        float4 v = *(const float4*)(g_qkv + (size_t)(g * 64 + r) * 384 + which * 192 + 64 + kv * 64 + dq * 4);
        *(float4*)((kv ? sv : sk) + r * 64 + dq * 4) = v;
    }
    __syncthreads();
    const int h = tid >> 6, i = tid & 63;
    float4 qv[4];
    const float4* qp = (const float4*)(g_qkv + (size_t)(g * 64 + i) * 384 + which * 192 + h * 16);
#pragma unroll
    for (int u = 0; u < 4; u++) {
        qv[u] = qp[u];
        qv[u].x *= 0.25f; qv[u].y *= 0.25f; qv[u].z *= 0.25f; qv[u].w *= 0.25f;
    }
    const float4* K4 = (const float4*)sk + h * 4;
    const float4* V4 = (const float4*)sv + h * 4;
    float sum = 0.f;
    float4 o[4];
#pragma unroll
    for (int u = 0; u < 4; u++) o[u] = make_float4(0.f, 0.f, 0.f, 0.f);
    for (int j = 0; j < 64; j++) {
        const float4* kr = K4 + j * 16;
        float s = 0.f;
#pragma unroll
        for (int u = 0; u < 4; u++) {
            float4 k = kr[u];
            s += qv[u].x * k.x + qv[u].y * k.y + qv[u].z * k.z + qv[u].w * k.w;
        }
        float p = __expf(s);
        sum += p;
        const float4* vr = V4 + j * 16;
#pragma unroll
        for (int u = 0; u < 4; u++) {
            float4 v = vr[u];
            o[u].x += p * v.x; o[u].y += p * v.y; o[u].z += p * v.z; o[u].w += p * v.w;
        }
    }
    float inv = 1.f / sum;
    float4* op = (float4*)(g_att + (size_t)(g * 64 + i) * 128 + which * 64 + h * 16);
#pragma unroll
    for (int u = 0; u < 4; u++)
        op[u] = make_float4(o[u].x * inv, o[u].y * inv, o[u].z * inv, o[u].w * inv);
}

// ---- Kernel D: intra out-proj (TF32 MMA, occ-2) + softplus + sample + scatter ----
__global__ void __launch_bounds__(256, 2) k_intra_out_tc(
    const float* __restrict__ wmu, const float* __restrict__ bmu,
    const float* __restrict__ wsd, const float* __restrict__ bsd,
    const int* __restrict__ sets, const float* __restrict__ eps,
    float* __restrict__ out)
{
    __shared__ uint32_t As[128][40];
    __shared__ uint32_t Ws[64][40];
    const int tid = threadIdx.x;
    const int lane = tid & 31, warp = tid >> 5;
    const int wm = warp >> 1, wn = warp & 1;
    const int gid = lane >> 2, tg = lane & 3;
    const int t0 = blockIdx.x * 128;

    float acc[2][2][4][4];
#pragma unroll
    for (int p = 0; p < 2; p++)
#pragma unroll
        for (int i = 0; i < 2; i++)
#pragma unroll
            for (int j = 0; j < 4; j++)
#pragma unroll
                for (int u = 0; u < 4; u++) acc[p][i][j][u] = 0.f;

#pragma unroll
    for (int p = 0; p < 2; p++) {
        const float* wsrc = p ? wsd : wmu;
#pragma unroll
        for (int kc = 0; kc < 2; kc++) {
            int k0 = kc * 32;
#pragma unroll
            for (int l = 0; l < 4; l++) {
                int slot = tid + l * 256;
                int r = slot >> 3, kq = slot & 7;
                int base = ((kq >> 1) << 3) + (kq & 1);
                float4 va = *(const float4*)(g_att + (size_t)(t0 + r) * 128 + p * 64 + k0 + kq * 4);
                As[r][base+0] = f2tf32(va.x); As[r][base+2] = f2tf32(va.y);
                As[r][base+4] = f2tf32(va.z); As[r][base+6] = f2tf32(va.w);
            }
#pragma unroll
            for (int l = 0; l < 2; l++) {
                int s2 = tid + l * 256;
                if (s2 < 512) {
                    int r = s2 >> 3, kq = s2 & 7;
                    int base = ((kq >> 1) << 3) + (kq & 1);
                    float4 vw = *(const float4*)(wsrc + (size_t)r * 64 + k0 + kq * 4);
                    Ws[r][base+0] = f2tf32(vw.x); Ws[r][base+2] = f2tf32(vw.y);
                    Ws[r][base+4] = f2tf32(vw.z); Ws[r][base+6] = f2tf32(vw.w);
                }
            }
            __syncthreads();
#pragma unroll
            for (int k8 = 0; k8 < 4; k8++) {
                int kb = k8 * 8 + 2 * tg;
                uint32_t a[2][4], b[4][2];
#pragma unroll
                for (int mt = 0; mt < 2; mt++) {
                    int row = wm * 32 + mt * 16;
                    uint2 pp = *(const uint2*)&As[row + gid][kb];
                    uint2 qq = *(const uint2*)&As[row + gid + 8][kb];
                    a[mt][0] = pp.x; a[mt][1] = qq.x; a[mt][2] = pp.y; a[mt][3] = qq.y;
                }
#pragma unroll
                for (int nt = 0; nt < 4; nt++) {
                    int col = wn * 32 + nt * 8;
                    uint2 qb = *(const uint2*)&Ws[col + gid][kb];
                    b[nt][0] = qb.x; b[nt][1] = qb.y;
                }
#pragma unroll
                for (int mt = 0; mt < 2; mt++)
#pragma unroll
                    for (int nt = 0; nt < 4; nt++)
                        mma_tf32(acc[p][mt][nt], a[mt], b[nt]);
            }
            __syncthreads();
        }
    }

    const size_t MU0 = (size_t)N_AG * 640, SD0 = MU0 + (size_t)N_AG * 128;
#pragma unroll
    for (int mt = 0; mt < 2; mt++) {
#pragma unroll
        for (int half = 0; half < 2; half++) {
            int row = t0 + wm * 32 + mt * 16 + gid + half * 8;
            int agent = sets[row];
#pragma unroll
            for (int nt = 0; nt < 4; nt++) {
                int col = wn * 32 + nt * 8 + 2 * tg;
                float m0v = acc[0][mt][nt][half * 2 + 0] + bmu[col];
                float m1v = acc[0][mt][nt][half * 2 + 1] + bmu[col + 1];
                float z0 = acc[1][mt][nt][half * 2 + 0] + bsd[col] - 5.f;
                float z1 = acc[1][mt][nt][half * 2 + 1] + bsd[col + 1] - 5.f;
                float s0 = (z0 > 20.f) ? z0 : log1pf(__expf(z0));
                float s1 = (z1 > 20.f) ? z1 : log1pf(__expf(z1));
                float2 ev = *(const float2*)(eps + (size_t)agent * 64 + col);
                float2 sa = make_float2(m0v + s0 * ev.x, m1v + s1 * ev.y);
                *(float2*)(out + (size_t)agent * 640 + 576 + col) = sa;
                *(float2*)(out + MU0 + (size_t)agent * 128 + col) = make_float2(m0v, m1v);
                *(float2*)(out + SD0 + (size_t)agent * 128 + col) = make_float2(s0, s1);
            }
        }
    }
}

// ---- Kernel E: softmax pooling per group ----
__global__ void __launch_bounds__(128) k_pool(const int* __restrict__ sets,
    const float* __restrict__ aw, const float* __restrict__ ab)
{
    __shared__ float P[64][65];
    __shared__ float logit[64];
    __shared__ float prob[64];
    const int g = blockIdx.x, tid = threadIdx.x;
#pragma unroll
    for (int l = 0; l < 8; l++) {
        int idx = tid + l * 128;
        int s = idx >> 4, dq = idx & 15;
        int agent = sets[g * 64 + s];
        float4 v = *(const float4*)(g_inter_emb + (size_t)agent * 64 + dq * 4);
        float* d = &P[s][dq * 4];
        d[0] = v.x; d[1] = v.y; d[2] = v.z; d[3] = v.w;
    }
    __syncthreads();
    if (tid < 64) {
        float a = ab[0];
#pragma unroll 8
        for (int d = 0; d < 64; d++) a += P[tid][d] * aw[d];
        logit[tid] = a;
    }
    __syncthreads();
    float mx = -1e30f;
    for (int s = 0; s < 64; s++) mx = fmaxf(mx, logit[s]);
    if (tid < 64) prob[tid] = __expf(logit[tid] - mx);
    __syncthreads();
    float sum = 0.f;
    for (int s = 0; s < 64; s++) sum += prob[s];
    if (tid < 64) {
        float acc = 0.f;
        for (int s = 0; s < 64; s++) acc += prob[s] * P[s][tid];
        g_pooled[g * 64 + tid] = acc / sum;
    }
}

// ---- Kernel F: inter QKV GEMM (small, fp32) ----
__global__ void __launch_bounds__(256) k_qkv_inter_k(
    const float* __restrict__ wmu, const float* __restrict__ bmu,
    const float* __restrict__ wsd, const float* __restrict__ bsd)
{
    __shared__ float As[16][132];
    __shared__ float Ws[16][132];
    const int tid = threadIdx.x, tx = tid & 15, ty = tid >> 4;
    const int m0 = blockIdx.x * 128, j0 = blockIdx.y * 128;
    float acc[8][8];
#pragma unroll
    for (int i = 0; i < 8; i++)
#pragma unroll
        for (int j = 0; j < 8; j++) acc[i][j] = 0.f;
    for (int k0 = 0; k0 < 64; k0 += 16) {
#pragma unroll
        for (int l = 0; l < 2; l++) {
            int idx = tid + l * 256;
            int r = idx >> 2, kq = idx & 3;
            float4 va = *(const float4*)(g_pooled + (size_t)(m0 + r) * 64 + k0 + kq * 4);
            As[kq*4+0][r] = va.x; As[kq*4+1][r] = va.y; As[kq*4+2][r] = va.z; As[kq*4+3][r] = va.w;
            int j = j0 + r;
            const float* wr = (j < 192) ? (wmu + (size_t)j * 64) : (wsd + (size_t)(j - 192) * 64);
            float4 vw = *(const float4*)(wr + k0 + kq * 4);
            Ws[kq*4+0][r] = vw.x; Ws[kq*4+1][r] = vw.y; Ws[kq*4+2][r] = vw.z; Ws[kq*4+3][r] = vw.w;
        }
        __syncthreads();
#pragma unroll
        for (int kk = 0; kk < 16; kk++) {
            float4 a0 = *(const float4*)&As[kk][ty * 8];
            float4 a1 = *(const float4*)&As[kk][ty * 8 + 4];
            float4 b0 = *(const float4*)&Ws[kk][tx * 8];
            float4 b1 = *(const float4*)&Ws[kk][tx * 8 + 4];
            float a[8] = {a0.x,a0.y,a0.z,a0.w,a1.x,a1.y,a1.z,a1.w};
            float b[8] = {b0.x,b0.y,b0.z,b0.w,b1.x,b1.y,b1.z,b1.w};
#pragma unroll
            for (int i = 0; i < 8; i++)
#pragma unroll
                for (int j = 0; j < 8; j++) acc[i][j] += a[i] * b[j];
        }
        __syncthreads();
    }
#pragma unroll
    for (int i = 0; i < 8; i++) {
        int m = m0 + ty * 8 + i;
#pragma unroll
        for (int jj = 0; jj < 8; jj += 4) {
            int j = j0 + tx * 8 + jj;
            const float* bb = (j < 192) ? (bmu + j) : (bsd + j - 192);
            float4 v = make_float4(acc[i][jj]+bb[0], acc[i][jj+1]+bb[1], acc[i][jj+2]+bb[2], acc[i][jj+3]+bb[3]);
            *(float4*)(g_qkv_inter + (size_t)m * 384 + j) = v;
        }
    }
}

// ---- Kernel G: inter attention over L=1024, single pass ----
__global__ void __launch_bounds__(256) k_inter_attn()
{
    __shared__ float ks[128 * 16];
    __shared__ float vs[128 * 16];
    const int bi = blockIdx.x;
    const int which = bi >> 4, h = (bi >> 2) & 3, quarter = bi & 3;
    const int tid = threadIdx.x;
    const int q = quarter * 256 + tid;
    float4 qv[4];
    const float4* qp = (const float4*)(g_qkv_inter + (size_t)q * 384 + which * 192 + h * 16);
#pragma unroll
    for (int u = 0; u < 4; u++) {
        qv[u] = qp[u];
        qv[u].x *= 0.25f; qv[u].y *= 0.25f; qv[u].z *= 0.25f; qv[u].w *= 0.25f;
    }
    float l = 0.f;
    float4 o[4];
#pragma unroll
    for (int u = 0; u < 4; u++) o[u] = make_float4(0.f, 0.f, 0.f, 0.f);
    for (int j0 = 0; j0 < 1024; j0 += 128) {
        __syncthreads();
#pragma unroll
        for (int li = 0; li < 4; li++) {
            int idx = tid + li * 256;
            int kv = idx >> 9, r = (idx >> 2) & 127, dq = idx & 3;
            float4 v = *(const float4*)(g_qkv_inter + (size_t)(j0 + r) * 384 + which * 192 + 64 + kv * 64 + h * 16 + dq * 4);
            *(float4*)((kv ? vs : ks) + r * 16 + dq * 4) = v;
        }
        __syncthreads();
        for (int j = 0; j < 128; j++) {
            const float4* kr = (const float4*)(ks + j * 16);
            float s = 0.f;
#pragma unroll
            for (int u = 0; u < 4; u++) {
                float4 k = kr[u];
                s += qv[u].x * k.x + qv[u].y * k.y + qv[u].z * k.z + qv[u].w * k.w;
            }
            float p = __expf(s);
            l += p;
            const float4* vr = (const float4*)(vs + j * 16);
#pragma unroll
            for (int u = 0; u < 4; u++) {
                float4 v = vr[u];
                o[u].x += p * v.x; o[u].y += p * v.y;
                o[u].z += p * v.z; o[u].w += p * v.w;
            }
        }
    }
    float inv = 1.f / l;
    float4* op = (float4*)(g_att_inter + (size_t)q * 128 + which * 64 + h * 16);
#pragma unroll
    for (int u = 0; u < 4; u++)
        op[u] = make_float4(o[u].x * inv, o[u].y * inv, o[u].z * inv, o[u].w * inv);
}

// ---- Kernel H: inter out-proj + softplus + sample + broadcast ----
__global__ void __launch_bounds__(256) k_inter_out(
    const float* __restrict__ wmu, const float* __restrict__ bmu,
    const float* __restrict__ wsd, const float* __restrict__ bsd,
    const int* __restrict__ sets, const float* __restrict__ eps,
    float* __restrict__ out)
{
    __shared__ float a[128];
    __shared__ float mu[64], sd[64], sa[64];
    const int g = blockIdx.x, tid = threadIdx.x;
    if (tid < 128) a[tid] = g_att_inter[(size_t)g * 128 + tid];
    __syncthreads();
    if (tid < 64) {
        float acc = bmu[tid];
        const float* w = wmu + (size_t)tid * 64;
#pragma unroll 8
        for (int d = 0; d < 64; d++) acc += a[d] * w[d];
        mu[tid] = acc;
    } else if (tid < 128) {
        int j = tid - 64;
        float acc = bsd[j];
        const float* w = wsd + (size_t)j * 64;
#pragma unroll 8
        for (int d = 0; d < 64; d++) acc += a[64 + d] * w[d];
        float z = acc - 5.f;
        sd[j] = (z > 20.f) ? z : log1pf(__expf(z));
    }
    __syncthreads();
    if (tid < 64) sa[tid] = mu[tid] + sd[tid] * eps[(size_t)g * 64 + tid];
    __syncthreads();
    const size_t MU0 = (size_t)N_AG * 640, SD0 = MU0 + (size_t)N_AG * 128;
    for (int idx = tid; idx < 64 * 192; idx += 256) {
        int i = idx / 192, c = idx % 192;
        int agent = sets[g * 64 + i];
        if (c < 64)       out[(size_t)agent * 640 + 512 + c] = sa[c];
        else if (c < 128) out[MU0 + (size_t)agent * 128 + 64 + (c - 64)] = mu[c - 64];
        else              out[SD0 + (size_t)agent * 128 + 64 + (c - 128)] = sd[c - 128];
    }
}

extern "C" void kernel_launch(void* const* d_in, const int* in_sizes, int n_in,
                              void* d_out, int out_size)
{
    (void)in_sizes; (void)n_in; (void)out_size;
    const float* obs   = (const float*)d_in[0];
    const int*   sets  = (const int*)d_in[1];
    const float* eps_a = (const float*)d_in[2];
    const float* eps_e = (const float*)d_in[3];
    const float* lw    = (const float*)d_in[4];
    const float* lb    = (const float*)d_in[5];
    const float* iew   = (const float*)d_in[6];
    const float* ieb   = (const float*)d_in[7];
    const float* aew   = (const float*)d_in[8];
    const float* aeb   = (const float*)d_in[9];
    const float* amu_iw = (const float*)d_in[10];
    const float* amu_ib = (const float*)d_in[11];
    const float* amu_ow = (const float*)d_in[12];
    const float* amu_ob = (const float*)d_in[13];
    const float* asd_iw = (const float*)d_in[14];
    const float* asd_ib = (const float*)d_in[15];
    const float* asd_ow = (const float*)d_in[16];
    const float* asd_ob = (const float*)d_in[17];
    const float* emu_iw = (const float*)d_in[18];
    const float* emu_ib = (const float*)d_in[19];
    const float* emu_ow = (const float*)d_in[20];
    const float* emu_ob = (const float*)d_in[21];
    const float* esd_iw = (const float*)d_in[22];
    const float* esd_ib = (const float*)d_in[23];
    const float* esd_ow = (const float*)d_in[24];
    const float* esd_ob = (const float*)d_in[25];
    const float* aw    = (const float*)d_in[26];
    const float* ab    = (const float*)d_in[27];
    float* out = (float*)d_out;

    k_emb_tc<<<dim3(512, 5), 256>>>(obs, lw, lb, iew, ieb, aew, aeb, out);
    k_qkv_tc<<<dim3(512, 3), 256>>>(sets, amu_iw, amu_ib, asd_iw, asd_ib);
    k_intra_attn<<<dim3(1024, 2), 256>>>();
    k_intra_out_tc<<<512, 256>>>(amu_ow, amu_ob, asd_ow, asd_ob, sets, eps_a, out);
    k_pool<<<1024, 128>>>(sets, aw, ab);
    k_qkv_inter_k<<<dim3(8, 3), 256>>>(emu_iw, emu_ib, esd_iw, esd_ib);
    k_inter_attn<<<32, 256>>>();
    k_inter_out<<<1024, 256>>>(emu_ow, emu_ob, esd_ow, esd_ob, sets, eps_e, out);
}

// round 9
// speedup vs baseline: 1.0547x; 1.0547x over previous
#include <cuda_runtime.h>
#include <math.h>
#include <stdint.h>

#define N_AG 65536
#define G_NUM 1024

static __device__ float g_inter_emb[(size_t)N_AG * 64];
static __device__ float g_intra_emb[(size_t)N_AG * 64];
static __device__ float g_pooled[G_NUM * 64];
static __device__ float g_qkv_inter[G_NUM * 384];
static __device__ float g_att_inter[G_NUM * 128];

__device__ __forceinline__ uint32_t f2tf32(float x) {
    uint32_t u;
    asm("cvt.rna.tf32.f32 %0, %1;" : "=r"(u) : "f"(x));
    return u;
}

__device__ __forceinline__ void mma_tf32(float* c, const uint32_t* a, const uint32_t* b) {
    asm volatile("mma.sync.aligned.m16n8k8.row.col.f32.tf32.tf32.f32 "
        "{%0,%1,%2,%3}, {%4,%5,%6,%7}, {%8,%9}, {%0,%1,%2,%3};"
        : "+f"(c[0]), "+f"(c[1]), "+f"(c[2]), "+f"(c[3])
        : "r"(a[0]), "r"(a[1]), "r"(a[2]), "r"(a[3]), "r"(b[0]), "r"(b[1]));
}

// ================= Kernel A: embedding GEMM (TF32 MMA) — R4 config =================
__global__ void __launch_bounds__(256) k_emb_tc(const float* __restrict__ obs,
    const float* __restrict__ lw, const float* __restrict__ lb,
    const float* __restrict__ iew, const float* __restrict__ ieb,
    const float* __restrict__ aew, const float* __restrict__ aeb,
    float* __restrict__ out)
{
    __shared__ uint32_t As[128][36];
    __shared__ uint32_t Ws[128][36];
    const int tid = threadIdx.x;
    const int lane = tid & 31, warp = tid >> 5;
    const int wm = warp >> 2, wn = warp & 3;
    const int gid = lane >> 2, tg = lane & 3;
    const int m0 = blockIdx.x * 128, j0 = blockIdx.y * 128;

    float acc[4][4][4];
#pragma unroll
    for (int i = 0; i < 4; i++)
#pragma unroll
        for (int j = 0; j < 4; j++)
#pragma unroll
            for (int u = 0; u < 4; u++) acc[i][j][u] = 0.f;

    for (int k0 = 0; k0 < 256; k0 += 32) {
#pragma unroll
        for (int l = 0; l < 4; l++) {
            int slot = tid + l * 256;
            int r = slot >> 3, kq = slot & 7;
            float4 va = *(const float4*)(obs + (size_t)(m0 + r) * 256 + k0 + kq * 4);
            As[r][kq*4+0] = f2tf32(va.x); As[r][kq*4+1] = f2tf32(va.y);
            As[r][kq*4+2] = f2tf32(va.z); As[r][kq*4+3] = f2tf32(va.w);
            int j = j0 + r;
            const float* wr = (j < 512) ? (lw + (size_t)j * 256)
                            : (j < 576) ? (iew + (size_t)(j - 512) * 256)
                            : (aew + (size_t)(j - 576) * 256);
            float4 vw = *(const float4*)(wr + k0 + kq * 4);
            Ws[r][kq*4+0] = f2tf32(vw.x); Ws[r][kq*4+1] = f2tf32(vw.y);
            Ws[r][kq*4+2] = f2tf32(vw.z); Ws[r][kq*4+3] = f2tf32(vw.w);
        }
        __syncthreads();
#pragma unroll
        for (int k8 = 0; k8 < 4; k8++) {
            int kb = k8 * 8;
            uint32_t a[4][4], b[4][2];
#pragma unroll
            for (int mt = 0; mt < 4; mt++) {
                int row = wm * 64 + mt * 16;
                a[mt][0] = As[row + gid][kb + tg];
                a[mt][1] = As[row + gid + 8][kb + tg];
                a[mt][2] = As[row + gid][kb + tg + 4];
                a[mt][3] = As[row + gid + 8][kb + tg + 4];
            }
#pragma unroll
            for (int nt = 0; nt < 4; nt++) {
                int col = wn * 32 + nt * 8;
                b[nt][0] = Ws[col + gid][kb + tg];
                b[nt][1] = Ws[col + gid][kb + tg + 4];
            }
#pragma unroll
            for (int mt = 0; mt < 4; mt++)
#pragma unroll
                for (int nt = 0; nt < 4; nt++)
                    mma_tf32(acc[mt][nt], a[mt], b[nt]);
        }
        __syncthreads();
    }

#pragma unroll
    for (int mt = 0; mt < 4; mt++) {
#pragma unroll
        for (int nt = 0; nt < 4; nt++) {
            int col = j0 + wn * 32 + nt * 8 + 2 * tg;
#pragma unroll
            for (int half = 0; half < 2; half++) {
                int row = m0 + wm * 64 + mt * 16 + gid + half * 8;
                float v0 = acc[mt][nt][half * 2 + 0];
                float v1 = acc[mt][nt][half * 2 + 1];
                float2 r2;
                if (col < 512) {
                    r2.x = tanhf(v0 + lb[col]); r2.y = tanhf(v1 + lb[col + 1]);
                    *(float2*)(out + (size_t)row * 640 + col) = r2;
                } else if (col < 576) {
                    int c = col - 512;
                    r2.x = tanhf(v0 + ieb[c]); r2.y = tanhf(v1 + ieb[c + 1]);
                    *(float2*)(g_inter_emb + (size_t)row * 64 + c) = r2;
                } else {
                    int c = col - 576;
                    r2.x = tanhf(v0 + aeb[c]); r2.y = tanhf(v1 + aeb[c + 1]);
                    *(float2*)(g_intra_emb + (size_t)row * 64 + c) = r2;
                }
            }
        }
    }
}

// ======== Kernel B: fully fused intra path (QKV + attention + out-proj + pool) ========
// One block per group. Dynamic smem.
#define OFF_IE  4352
#define OFF_QKV 8704
#define OFF_ATT 33792
#define OFF_W   42496
#define OFF_LG  55552
#define OFF_PR  55616
#define SMEM_FUSED_FLOATS 55680

__global__ void __launch_bounds__(256) k_intra_fused(const int* __restrict__ sets,
    const float* __restrict__ wmu_in, const float* __restrict__ bmu_in,
    const float* __restrict__ wsd_in, const float* __restrict__ bsd_in,
    const float* __restrict__ wmu_out, const float* __restrict__ bmu_out,
    const float* __restrict__ wsd_out, const float* __restrict__ bsd_out,
    const float* __restrict__ aw, const float* __restrict__ ab,
    const float* __restrict__ eps, float* __restrict__ out)
{
    extern __shared__ float sm[];
    float* s_emb = sm;                 // [64][68]
    float* s_ie  = sm + OFF_IE;        // [64][68]
    float* s_qkv = sm + OFF_QKV;       // [2][64][196]
    float* s_att = sm + OFF_ATT;       // [2][64][68]
    float* s_w   = sm + OFF_W;         // [192][68] (or [2][64][68])
    float* s_lg  = sm + OFF_LG;        // [64]
    float* s_pr  = sm + OFF_PR;        // [64]

    const int g = blockIdx.x, tid = threadIdx.x;
    const int lane = tid & 31, warp = tid >> 5;
    const int gid = lane >> 2, tg = lane & 3;

    // ---- Phase A: gather member embeddings (intra + inter) ----
#pragma unroll
    for (int l = 0; l < 4; l++) {
        int idx = tid + l * 256;
        int r = idx >> 4, c4 = (idx & 15) * 4;
        int agent = sets[g * 64 + r];
        *(float4*)(s_emb + r * 68 + c4) = *(const float4*)(g_intra_emb + (size_t)agent * 64 + c4);
        *(float4*)(s_ie + r * 68 + c4)  = *(const float4*)(g_inter_emb + (size_t)agent * 64 + c4);
    }
    __syncthreads();

    // ---- Phase B: pool logits + stage W_in(mu) ----
    if (tid < 64) {
        float a = ab[0];
#pragma unroll 8
        for (int d = 0; d < 64; d++) a += s_ie[tid * 68 + d] * aw[d];
        s_lg[tid] = a;
    }
#pragma unroll
    for (int l = 0; l < 12; l++) {
        int idx = tid + l * 256;
        int r = idx >> 4, c4 = (idx & 15) * 4;
        *(float4*)(s_w + r * 68 + c4) = *(const float4*)(wmu_in + (size_t)r * 64 + c4);
    }
    __syncthreads();

    // ---- Phase C: pool probs + QKV(mu) MMA ----
    if (tid < 64) {
        float mx = -1e30f;
        for (int s = 0; s < 64; s++) mx = fmaxf(mx, s_lg[s]);
        s_pr[tid] = __expf(s_lg[tid] - mx);
    }
    {
        const int wm = warp >> 1, wn = warp & 1;
        float acc[12][4];
#pragma unroll
        for (int nt = 0; nt < 12; nt++)
#pragma unroll
            for (int u = 0; u < 4; u++) acc[nt][u] = 0.f;
#pragma unroll
        for (int k8 = 0; k8 < 8; k8++) {
            int kb = k8 * 8;
            uint32_t a[4];
            a[0] = f2tf32(s_emb[(wm*16+gid)*68 + kb+tg]);
            a[1] = f2tf32(s_emb[(wm*16+gid+8)*68 + kb+tg]);
            a[2] = f2tf32(s_emb[(wm*16+gid)*68 + kb+tg+4]);
            a[3] = f2tf32(s_emb[(wm*16+gid+8)*68 + kb+tg+4]);
#pragma unroll
            for (int nt = 0; nt < 12; nt++) {
                int col = wn * 96 + nt * 8;
                uint32_t b[2];
                b[0] = f2tf32(s_w[(col+gid)*68 + kb+tg]);
                b[1] = f2tf32(s_w[(col+gid)*68 + kb+tg+4]);
                mma_tf32(acc[nt], a, b);
            }
        }
#pragma unroll
        for (int nt = 0; nt < 12; nt++) {
            int col = wn * 96 + nt * 8 + 2 * tg;
            float b0 = bmu_in[col], b1 = bmu_in[col + 1];
            *(float2*)(s_qkv + (wm*16+gid)*196 + col)   = make_float2(acc[nt][0]+b0, acc[nt][1]+b1);
            *(float2*)(s_qkv + (wm*16+gid+8)*196 + col) = make_float2(acc[nt][2]+b0, acc[nt][3]+b1);
        }
    }
    __syncthreads();

    // ---- Phase D: pool finish + stage W_in(sd) ----
    if (tid < 64) {
        float sum = 0.f, acc = 0.f;
        for (int s = 0; s < 64; s++) sum += s_pr[s];
        for (int s = 0; s < 64; s++) acc += s_pr[s] * s_ie[s * 68 + tid];
        g_pooled[g * 64 + tid] = acc / sum;
    }
#pragma unroll
    for (int l = 0; l < 12; l++) {
        int idx = tid + l * 256;
        int r = idx >> 4, c4 = (idx & 15) * 4;
        *(float4*)(s_w + r * 68 + c4) = *(const float4*)(wsd_in + (size_t)r * 64 + c4);
    }
    __syncthreads();

    // ---- Phase E: QKV(sd) MMA ----
    {
        const int wm = warp >> 1, wn = warp & 1;
        float acc[12][4];
#pragma unroll
        for (int nt = 0; nt < 12; nt++)
#pragma unroll
            for (int u = 0; u < 4; u++) acc[nt][u] = 0.f;
#pragma unroll
        for (int k8 = 0; k8 < 8; k8++) {
            int kb = k8 * 8;
            uint32_t a[4];
            a[0] = f2tf32(s_emb[(wm*16+gid)*68 + kb+tg]);
            a[1] = f2tf32(s_emb[(wm*16+gid+8)*68 + kb+tg]);
            a[2] = f2tf32(s_emb[(wm*16+gid)*68 + kb+tg+4]);
            a[3] = f2tf32(s_emb[(wm*16+gid+8)*68 + kb+tg+4]);
#pragma unroll
            for (int nt = 0; nt < 12; nt++) {
                int col = wn * 96 + nt * 8;
                uint32_t b[2];
                b[0] = f2tf32(s_w[(col+gid)*68 + kb+tg]);
                b[1] = f2tf32(s_w[(col+gid)*68 + kb+tg+4]);
                mma_tf32(acc[nt], a, b);
            }
        }
#pragma unroll
        for (int nt = 0; nt < 12; nt++) {
            int col = wn * 96 + nt * 8 + 2 * tg;
            float b0 = bsd_in[col], b1 = bsd_in[col + 1];
            *(float2*)(s_qkv + 12544 + (wm*16+gid)*196 + col)   = make_float2(acc[nt][0]+b0, acc[nt][1]+b1);
            *(float2*)(s_qkv + 12544 + (wm*16+gid+8)*196 + col) = make_float2(acc[nt][2]+b0, acc[nt][3]+b1);
        }
    }
    __syncthreads();

    // ---- Phase F: stage W_out(mu,sd) + attention (both) ----
#pragma unroll
    for (int l = 0; l < 8; l++) {
        int idx = tid + l * 256;
        int w = idx >> 10, r = (idx >> 4) & 63, c4 = (idx & 15) * 4;
        *(float4*)(s_w + w * 4352 + r * 68 + c4) =
            *(const float4*)((w ? wsd_out : wmu_out) + (size_t)r * 64 + c4);
    }
    {
        const int h = tid >> 6, i = tid & 63;
#pragma unroll
        for (int w = 0; w < 2; w++) {
            const float* base = s_qkv + w * 12544;
            float4 qv[4];
            const float4* qp = (const float4*)(base + i * 196 + h * 16);
#pragma unroll
            for (int u = 0; u < 4; u++) {
                qv[u] = qp[u];
                qv[u].x *= 0.25f; qv[u].y *= 0.25f; qv[u].z *= 0.25f; qv[u].w *= 0.25f;
            }
            float sum = 0.f;
            float4 o[4];
#pragma unroll
            for (int u = 0; u < 4; u++) o[u] = make_float4(0.f, 0.f, 0.f, 0.f);
            for (int j = 0; j < 64; j++) {
                const float4* kr = (const float4*)(base + j * 196 + 64 + h * 16);
                float s = 0.f;
#pragma unroll
                for (int u = 0; u < 4; u++) {
                    float4 k = kr[u];
                    s += qv[u].x * k.x + qv[u].y * k.y + qv[u].z * k.z + qv[u].w * k.w;
                }
                float p = __expf(s);
                sum += p;
                const float4* vr = (const float4*)(base + j * 196 + 128 + h * 16);
#pragma unroll
                for (int u = 0; u < 4; u++) {
                    float4 v = vr[u];
                    o[u].x += p * v.x; o[u].y += p * v.y; o[u].z += p * v.z; o[u].w += p * v.w;
                }
            }
            float inv = 1.f / sum;
            float4* op = (float4*)(s_att + w * 4352 + i * 68 + h * 16);
#pragma unroll
            for (int u = 0; u < 4; u++)
                op[u] = make_float4(o[u].x * inv, o[u].y * inv, o[u].z * inv, o[u].w * inv);
        }
    }
    __syncthreads();

    // ---- Phase G: out-proj MMA (mu & sd) + softplus + sample + scatter ----
    {
        const int wm = warp >> 1, wn = warp & 1;
        float am[2][4][4];
#pragma unroll
        for (int w = 0; w < 2; w++)
#pragma unroll
            for (int nt = 0; nt < 4; nt++)
#pragma unroll
                for (int u = 0; u < 4; u++) am[w][nt][u] = 0.f;
#pragma unroll
        for (int w = 0; w < 2; w++) {
            const float* A = s_att + w * 4352;
            const float* B = s_w + w * 4352;
#pragma unroll
            for (int k8 = 0; k8 < 8; k8++) {
                int kb = k8 * 8;
                uint32_t a[4];
                a[0] = f2tf32(A[(wm*16+gid)*68 + kb+tg]);
                a[1] = f2tf32(A[(wm*16+gid+8)*68 + kb+tg]);
                a[2] = f2tf32(A[(wm*16+gid)*68 + kb+tg+4]);
                a[3] = f2tf32(A[(wm*16+gid+8)*68 + kb+tg+4]);
#pragma unroll
                for (int nt = 0; nt < 4; nt++) {
                    int col = wn * 32 + nt * 8;
                    uint32_t b[2];
                    b[0] = f2tf32(B[(col+gid)*68 + kb+tg]);
                    b[1] = f2tf32(B[(col+gid)*68 + kb+tg+4]);
                    mma_tf32(am[w][nt], a, b);
                }
            }
        }
        const size_t MU0 = (size_t)N_AG * 640, SD0 = MU0 + (size_t)N_AG * 128;
#pragma unroll
        for (int nt = 0; nt < 4; nt++) {
            int col = wn * 32 + nt * 8 + 2 * tg;
#pragma unroll
            for (int half = 0; half < 2; half++) {
                int row = wm * 16 + gid + half * 8;
                int agent = sets[g * 64 + row];
                float m0v = am[0][nt][half*2+0] + bmu_out[col];
                float m1v = am[0][nt][half*2+1] + bmu_out[col + 1];
                float z0 = am[1][nt][half*2+0] + bsd_out[col] - 5.f;
                float z1 = am[1][nt][half*2+1] + bsd_out[col + 1] - 5.f;
                float s0 = (z0 > 20.f) ? z0 : log1pf(__expf(z0));
                float s1 = (z1 > 20.f) ? z1 : log1pf(__expf(z1));
                float2 ev = *(const float2*)(eps + (size_t)agent * 64 + col);
                float2 sa = make_float2(m0v + s0 * ev.x, m1v + s1 * ev.y);
                *(float2*)(out + (size_t)agent * 640 + 576 + col) = sa;
                *(float2*)(out + MU0 + (size_t)agent * 128 + col) = make_float2(m0v, m1v);
                *(float2*)(out + SD0 + (size_t)agent * 128 + col) = make_float2(s0, s1);
            }
        }
    }
}

// ---- Kernel F: inter QKV GEMM (small, fp32) ----
__global__ void __launch_bounds__(256) k_qkv_inter_k(
    const float* __restrict__ wmu, const float* __restrict__ bmu,
    const float* __restrict__ wsd, const float* __restrict__ bsd)
{
    __shared__ float As[16][132];
    __shared__ float Ws[16][132];
    const int tid = threadIdx.x, tx = tid & 15, ty = tid >> 4;
    const int m0 = blockIdx.x * 128, j0 = blockIdx.y * 128;
    float acc[8][8];
#pragma unroll
    for (int i = 0; i < 8; i++)
#pragma unroll
        for (int j = 0; j < 8; j++) acc[i][j] = 0.f;
    for (int k0 = 0; k0 < 64; k0 += 16) {
#pragma unroll
        for (int l = 0; l < 2; l++) {
            int idx = tid + l * 256;
            int r = idx >> 2, kq = idx & 3;
            float4 va = *(const float4*)(g_pooled + (size_t)(m0 + r) * 64 + k0 + kq * 4);
            As[kq*4+0][r] = va.x; As[kq*4+1][r] = va.y; As[kq*4+2][r] = va.z; As[kq*4+3][r] = va.w;
            int j = j0 + r;
            const float* wr = (j < 192) ? (wmu + (size_t)j * 64) : (wsd + (size_t)(j - 192) * 64);
            float4 vw = *(const float4*)(wr + k0 + kq * 4);
            Ws[kq*4+0][r] = vw.x; Ws[kq*4+1][r] = vw.y; Ws[kq*4+2][r] = vw.z; Ws[kq*4+3][r] = vw.w;
        }
        __syncthreads();
#pragma unroll
        for (int kk = 0; kk < 16; kk++) {
            float4 a0 = *(const float4*)&As[kk][ty * 8];
            float4 a1 = *(const float4*)&As[kk][ty * 8 + 4];
            float4 b0 = *(const float4*)&Ws[kk][tx * 8];
            float4 b1 = *(const float4*)&Ws[kk][tx * 8 + 4];
            float a[8] = {a0.x,a0.y,a0.z,a0.w,a1.x,a1.y,a1.z,a1.w};
            float b[8] = {b0.x,b0.y,b0.z,b0.w,b1.x,b1.y,b1.z,b1.w};
#pragma unroll
            for (int i = 0; i < 8; i++)
#pragma unroll
                for (int j = 0; j < 8; j++) acc[i][j] += a[i] * b[j];
        }
        __syncthreads();
    }
#pragma unroll
    for (int i = 0; i < 8; i++) {
        int m = m0 + ty * 8 + i;
#pragma unroll
        for (int jj = 0; jj < 8; jj += 4) {
            int j = j0 + tx * 8 + jj;
            const float* bb = (j < 192) ? (bmu + j) : (bsd + j - 192);
            float4 v = make_float4(acc[i][jj]+bb[0], acc[i][jj+1]+bb[1], acc[i][jj+2]+bb[2], acc[i][jj+3]+bb[3]);
            *(float4*)(g_qkv_inter + (size_t)m * 384 + j) = v;
        }
    }
}

// ---- Kernel G: inter attention over L=1024, single pass ----
__global__ void __launch_bounds__(256) k_inter_attn()
{
    __shared__ float ks[128 * 16];
    __shared__ float vs[128 * 16];
    const int bi = blockIdx.x;
    const int which = bi >> 4, h = (bi >> 2) & 3, quarter = bi & 3;
    const int tid = threadIdx.x;
    const int q = quarter * 256 + tid;
    float4 qv[4];
    const float4* qp = (const float4*)(g_qkv_inter + (size_t)q * 384 + which * 192 + h * 16);
#pragma unroll
    for (int u = 0; u < 4; u++) {
        qv[u] = qp[u];
        qv[u].x *= 0.25f; qv[u].y *= 0.25f; qv[u].z *= 0.25f; qv[u].w *= 0.25f;
    }
    float l = 0.f;
    float4 o[4];
#pragma unroll
    for (int u = 0; u < 4; u++) o[u] = make_float4(0.f, 0.f, 0.f, 0.f);
    for (int j0 = 0; j0 < 1024; j0 += 128) {
        __syncthreads();
#pragma unroll
        for (int li = 0; li < 4; li++) {
            int idx = tid + li * 256;
            int kv = idx >> 9, r = (idx >> 2) & 127, dq = idx & 3;
            float4 v = *(const float4*)(g_qkv_inter + (size_t)(j0 + r) * 384 + which * 192 + 64 + kv * 64 + h * 16 + dq * 4);
            *(float4*)((kv ? vs : ks) + r * 16 + dq * 4) = v;
        }
        __syncthreads();
        for (int j = 0; j < 128; j++) {
            const float4* kr = (const float4*)(ks + j * 16);
            float s = 0.f;
#pragma unroll
            for (int u = 0; u < 4; u++) {
                float4 k = kr[u];
                s += qv[u].x * k.x + qv[u].y * k.y + qv[u].z * k.z + qv[u].w * k.w;
            }
            float p = __expf(s);
            l += p;
            const float4* vr = (const float4*)(vs + j * 16);
#pragma unroll
            for (int u = 0; u < 4; u++) {
                float4 v = vr[u];
                o[u].x += p * v.x; o[u].y += p * v.y;
                o[u].z += p * v.z; o[u].w += p * v.w;
            }
        }
    }
    float inv = 1.f / l;
    float4* op = (float4*)(g_att_inter + (size_t)q * 128 + which * 64 + h * 16);
#pragma unroll
    for (int u = 0; u < 4; u++)
        op[u] = make_float4(o[u].x * inv, o[u].y * inv, o[u].z * inv, o[u].w * inv);
}

// ---- Kernel H: inter out-proj + softplus + sample + broadcast ----
__global__ void __launch_bounds__(256) k_inter_out(
    const float* __restrict__ wmu, const float* __restrict__ bmu,
    const float* __restrict__ wsd, const float* __restrict__ bsd,
    const int* __restrict__ sets, const float* __restrict__ eps,
    float* __restrict__ out)
{
    __shared__ float a[128];
    __shared__ float mu[64], sd[64], sa[64];
    const int g = blockIdx.x, tid = threadIdx.x;
    if (tid < 128) a[tid] = g_att_inter[(size_t)g * 128 + tid];
    __syncthreads();
    if (tid < 64) {
        float acc = bmu[tid];
        const float* w = wmu + (size_t)tid * 64;
#pragma unroll 8
        for (int d = 0; d < 64; d++) acc += a[d] * w[d];
        mu[tid] = acc;
    } else if (tid < 128) {
        int j = tid - 64;
        float acc = bsd[j];
        const float* w = wsd + (size_t)j * 64;
#pragma unroll 8
        for (int d = 0; d < 64; d++) acc += a[64 + d] * w[d];
        float z = acc - 5.f;
        sd[j] = (z > 20.f) ? z : log1pf(__expf(z));
    }
    __syncthreads();
    if (tid < 64) sa[tid] = mu[tid] + sd[tid] * eps[(size_t)g * 64 + tid];
    __syncthreads();
    const size_t MU0 = (size_t)N_AG * 640, SD0 = MU0 + (size_t)N_AG * 128;
    for (int idx = tid; idx < 64 * 192; idx += 256) {
        int i = idx / 192, c = idx % 192;
        int agent = sets[g * 64 + i];
        if (c < 64)       out[(size_t)agent * 640 + 512 + c] = sa[c];
        else if (c < 128) out[MU0 + (size_t)agent * 128 + 64 + (c - 64)] = mu[c - 64];
        else              out[SD0 + (size_t)agent * 128 + 64 + (c - 128)] = sd[c - 128];
    }
}

extern "C" void kernel_launch(void* const* d_in, const int* in_sizes, int n_in,
                              void* d_out, int out_size)
{
    (void)in_sizes; (void)n_in; (void)out_size;
    const float* obs   = (const float*)d_in[0];
    const int*   sets  = (const int*)d_in[1];
    const float* eps_a = (const float*)d_in[2];
    const float* eps_e = (const float*)d_in[3];
    const float* lw    = (const float*)d_in[4];
    const float* lb    = (const float*)d_in[5];
    const float* iew   = (const float*)d_in[6];
    const float* ieb   = (const float*)d_in[7];
    const float* aew   = (const float*)d_in[8];
    const float* aeb   = (const float*)d_in[9];
    const float* amu_iw = (const float*)d_in[10];
    const float* amu_ib = (const float*)d_in[11];
    const float* amu_ow = (const float*)d_in[12];
    const float* amu_ob = (const float*)d_in[13];
    const float* asd_iw = (const float*)d_in[14];
    const float* asd_ib = (const float*)d_in[15];
    const float* asd_ow = (const float*)d_in[16];
    const float* asd_ob = (const float*)d_in[17];
    const float* emu_iw = (const float*)d_in[18];
    const float* emu_ib = (const float*)d_in[19];
    const float* emu_ow = (const float*)d_in[20];
    const float* emu_ob = (const float*)d_in[21];
    const float* esd_iw = (const float*)d_in[22];
    const float* esd_ib = (const float*)d_in[23];
    const float* esd_ow = (const float*)d_in[24];
    const float* esd_ob = (const float*)d_in[25];
    const float* aw    = (const float*)d_in[26];
    const float* ab    = (const float*)d_in[27];
    float* out = (float*)d_out;

    const int smem_bytes = SMEM_FUSED_FLOATS * 4;
    cudaFuncSetAttribute(k_intra_fused, cudaFuncAttributeMaxDynamicSharedMemorySize, smem_bytes);

    k_emb_tc<<<dim3(512, 5), 256>>>(obs, lw, lb, iew, ieb, aew, aeb, out);
    k_intra_fused<<<1024, 256, smem_bytes>>>(sets,
        amu_iw, amu_ib, asd_iw, asd_ib,
        amu_ow, amu_ob, asd_ow, asd_ob,
        aw, ab, eps_a, out);
    k_qkv_inter_k<<<dim3(8, 3), 256>>>(emu_iw, emu_ib, esd_iw, esd_ib);
    k_inter_attn<<<32, 256>>>();
    k_inter_out<<<1024, 256>>>(emu_ow, emu_ob, esd_ow, esd_ob, sets, eps_e, out);
}